// round 9
// baseline (speedup 1.0000x reference)
#include <cuda_runtime.h>
#include <cuda_bf16.h>
#include <cstdint>

// ---------------------------------------------------------------------------
// Problem dims (fixed by the dataset)
// ---------------------------------------------------------------------------
#define N_BATCH 32
#define B_OBJ   36
#define D_DIM   2048
#define Q_DIM   1024
#define NB      (N_BATCH * B_OBJ)   // 1152

// Scratch (device globals)
__device__ float          g_qe [N_BATCH * D_DIM];
__device__ float          g_g  [NB * D_DIM];        // GEMM1 out (fp32, for pair)
__device__ __nv_bfloat16  g_uh [NB * D_DIM];        // (v*qe) hi
__device__ __nv_bfloat16  g_ul [NB * D_DIM];        // (v*qe) lo
__device__ __nv_bfloat16  g_xh [NB * D_DIM];        // pair-out hi
__device__ __nv_bfloat16  g_xl [NB * D_DIM];        // pair-out lo
__device__ __nv_bfloat16  g_W1h[D_DIM * D_DIM];     // W1^T hi  [N][K]
__device__ __nv_bfloat16  g_W1l[D_DIM * D_DIM];
__device__ __nv_bfloat16  g_W2h[D_DIM * D_DIM];
__device__ __nv_bfloat16  g_W2l[D_DIM * D_DIM];

// ---------------------------------------------------------------------------
// Helpers
// ---------------------------------------------------------------------------
__device__ __forceinline__ uint32_t smem_u32(const void* p) {
    uint32_t a;
    asm("{ .reg .u64 t; cvta.to.shared.u64 t, %1; cvt.u32.u64 %0, t; }"
        : "=r"(a) : "l"(p));
    return a;
}

__device__ __forceinline__ void ldmatrix_x4(uint32_t& r0, uint32_t& r1,
                                            uint32_t& r2, uint32_t& r3,
                                            uint32_t addr) {
    asm volatile("ldmatrix.sync.aligned.m8n8.x4.shared.b16 {%0,%1,%2,%3}, [%4];"
                 : "=r"(r0), "=r"(r1), "=r"(r2), "=r"(r3) : "r"(addr));
}

__device__ __forceinline__ void ldmatrix_x2(uint32_t& r0, uint32_t& r1,
                                            uint32_t addr) {
    asm volatile("ldmatrix.sync.aligned.m8n8.x2.shared.b16 {%0,%1}, [%2];"
                 : "=r"(r0), "=r"(r1) : "r"(addr));
}

__device__ __forceinline__ void mma_bf16(float& c0, float& c1, float& c2, float& c3,
                                         uint32_t a0, uint32_t a1, uint32_t a2, uint32_t a3,
                                         uint32_t b0, uint32_t b1) {
    asm volatile(
        "mma.sync.aligned.m16n8k16.row.col.f32.bf16.bf16.f32 "
        "{%0,%1,%2,%3}, {%4,%5,%6,%7}, {%8,%9}, {%0,%1,%2,%3};"
        : "+f"(c0), "+f"(c1), "+f"(c2), "+f"(c3)
        : "r"(a0), "r"(a1), "r"(a2), "r"(a3), "r"(b0), "r"(b1));
}

__device__ __forceinline__ void cp_async16(uint32_t dst, const void* src) {
    asm volatile("cp.async.cg.shared.global [%0], [%1], 16;"
                 :: "r"(dst), "l"(src) : "memory");
}
#define CP_COMMIT() asm volatile("cp.async.commit_group;" ::: "memory")
#define CP_WAIT2()  asm volatile("cp.async.wait_group 2;"  ::: "memory")

// Split fp32 -> bf16 hi + bf16 lo
__device__ __forceinline__ void split1(float x, __nv_bfloat16& h, __nv_bfloat16& l) {
    h = __float2bfloat16(x);
    l = __float2bfloat16(x - __bfloat162float(h));
}

// ---------------------------------------------------------------------------
// Kernel 1: qe[n,d] = relu(sum_k q[n,k] * W3[k,d] + b3[d])
// ---------------------------------------------------------------------------
__global__ __launch_bounds__(256)
void qe_kernel(const float* __restrict__ q,
               const float* __restrict__ W3,
               const float* __restrict__ b3) {
    int gid = blockIdx.x * 256 + threadIdx.x;       // 0..16383
    int d  = gid & (D_DIM - 1);
    int n0 = (gid >> 11) * 4;
    float a0 = 0.f, a1 = 0.f, a2 = 0.f, a3 = 0.f;
    const float* q0 = q + (n0 + 0) * Q_DIM;
    const float* q1 = q + (n0 + 1) * Q_DIM;
    const float* q2 = q + (n0 + 2) * Q_DIM;
    const float* q3 = q + (n0 + 3) * Q_DIM;
    #pragma unroll 4
    for (int k = 0; k < Q_DIM; k++) {
        float w = W3[k * D_DIM + d];
        a0 += q0[k] * w; a1 += q1[k] * w; a2 += q2[k] * w; a3 += q3[k] * w;
    }
    float b = b3[d];
    g_qe[(n0 + 0) * D_DIM + d] = fmaxf(a0 + b, 0.f);
    g_qe[(n0 + 1) * D_DIM + d] = fmaxf(a1 + b, 0.f);
    g_qe[(n0 + 2) * D_DIM + d] = fmaxf(a2 + b, 0.f);
    g_qe[(n0 + 3) * D_DIM + d] = fmaxf(a3 + b, 0.f);
}

// ---------------------------------------------------------------------------
// Kernel 2: fused transpose + bf16 split: W [K][N] -> Wt_hi/lo [N][K]
// ---------------------------------------------------------------------------
__global__ __launch_bounds__(256)
void wsplit(const float* __restrict__ in,
            __nv_bfloat16* __restrict__ oh,
            __nv_bfloat16* __restrict__ ol) {
    __shared__ float tile[32][33];
    int x = blockIdx.x * 32 + threadIdx.x;
    int y = blockIdx.y * 32 + threadIdx.y;
    #pragma unroll
    for (int j = 0; j < 32; j += 8)
        tile[threadIdx.y + j][threadIdx.x] = in[(y + j) * D_DIM + x];
    __syncthreads();
    x = blockIdx.y * 32 + threadIdx.x;   // k index in output
    y = blockIdx.x * 32 + threadIdx.y;   // n index in output
    #pragma unroll
    for (int j = 0; j < 32; j += 8) {
        float v = tile[threadIdx.x][threadIdx.y + j];
        __nv_bfloat16 h, l;
        split1(v, h, l);
        oh[(size_t)(y + j) * D_DIM + x] = h;
        ol[(size_t)(y + j) * D_DIM + x] = l;
    }
}

// ---------------------------------------------------------------------------
// Kernel 3: u = v * qe  -> split into g_uh / g_ul
// ---------------------------------------------------------------------------
__global__ __launch_bounds__(256)
void usplit(const float* __restrict__ v) {
    int idx4 = blockIdx.x * 256 + threadIdx.x;      // float4 index
    int idx = idx4 * 4;
    if (idx >= NB * D_DIM) return;
    int row = idx / D_DIM;
    int d   = idx & (D_DIM - 1);
    int n   = row / B_OBJ;
    float4 vv = *reinterpret_cast<const float4*>(v + idx);
    float4 qq = *reinterpret_cast<const float4*>(g_qe + n * D_DIM + d);
    float u0 = vv.x * qq.x, u1 = vv.y * qq.y, u2 = vv.z * qq.z, u3 = vv.w * qq.w;
    __nv_bfloat16 h0, h1, h2, h3, l0, l1, l2, l3;
    split1(u0, h0, l0); split1(u1, h1, l1);
    split1(u2, h2, l2); split1(u3, h3, l3);
    __nv_bfloat162 ph0(h0, h1), ph1(h2, h3), pl0(l0, l1), pl1(l2, l3);
    *reinterpret_cast<__nv_bfloat162*>(g_uh + idx)     = ph0;
    *reinterpret_cast<__nv_bfloat162*>(g_uh + idx + 2) = ph1;
    *reinterpret_cast<__nv_bfloat162*>(g_ul + idx)     = pl0;
    *reinterpret_cast<__nv_bfloat162*>(g_ul + idx + 2) = pl1;
}

// ---------------------------------------------------------------------------
// GEMM: C[1152,2048] = A @ B^T using pre-split bf16 hi/lo operands.
// A rows [M][K] (hi/lo), B rows [N][K] (hi/lo).  3-term: Ah*Bh + Ah*Bl + Al*Bh.
// CTA 128x128x32, 512 threads (16 warps, 4x4), warp tile 32x32.
// cp.async 4-stage pipeline. SMEM rows padded to 80B (conflict-free ldmatrix).
// ---------------------------------------------------------------------------
constexpr int ROWB   = 80;
constexpr int TILEB  = 128 * ROWB;        // 10240
constexpr int STAGEB = 4 * TILEB;         // 40960 (Ah, Al, Bh, Bl)
constexpr int SMEM_GEMM = 4 * STAGEB;     // 163840

template<bool BIASRELU>
__global__ __launch_bounds__(512, 1)
void bf16_gemm(const __nv_bfloat16* __restrict__ Ah,
               const __nv_bfloat16* __restrict__ Al,
               const __nv_bfloat16* __restrict__ Bh,
               const __nv_bfloat16* __restrict__ Bl,
               const float* __restrict__ bias,
               float* __restrict__ C) {
    extern __shared__ char sm[];
    const uint32_t sbase = smem_u32(sm);

    const int tid  = threadIdx.x;
    const int wid  = tid >> 5;
    const int lane = tid & 31;
    const int wm   = wid >> 2;                 // 0..3
    const int wn   = wid & 3;                  // 0..3
    const int m0   = blockIdx.y * 128;
    const int n0   = blockIdx.x * 128;
    constexpr int K = 2048;
    constexpr int ITERS = K / 32;              // 64

    // cp.async assignment: row = tid>>2, chunk c = tid&3 (16B each), all 4 tiles
    const int lr = tid >> 2;
    const int lc = tid & 3;
    const char* gAh = (const char*)(Ah + (size_t)(m0 + lr) * K) + lc * 16;
    const char* gAl = (const char*)(Al + (size_t)(m0 + lr) * K) + lc * 16;
    const char* gBh = (const char*)(Bh + (size_t)(n0 + lr) * K) + lc * 16;
    const char* gBl = (const char*)(Bl + (size_t)(n0 + lr) * K) + lc * 16;
    const uint32_t sdst = sbase + lr * ROWB + lc * 16;

    auto issue = [&](int it) {
        if (it < ITERS) {
            const uint32_t st = (it & 3) * STAGEB;
            const int gk = it * 64;            // byte offset along K (32 bf16)
            cp_async16(sdst + st,             gAh + gk);
            cp_async16(sdst + st + TILEB,     gAl + gk);
            cp_async16(sdst + st + 2 * TILEB, gBh + gk);
            cp_async16(sdst + st + 3 * TILEB, gBl + gk);
        }
        CP_COMMIT();
    };

    // ldmatrix per-lane offsets
    const uint32_t a_off = (wm * 32 + (lane & 15)) * ROWB + ((lane >> 4) & 1) * 16;
    const uint32_t b_off = (wn * 32 + (lane & 7)) * ROWB + ((lane >> 3) & 1) * 16;

    float c[2][4][4];
    #pragma unroll
    for (int i = 0; i < 2; i++)
        #pragma unroll
        for (int j = 0; j < 4; j++)
            #pragma unroll
            for (int k = 0; k < 4; k++) c[i][j][k] = 0.f;

    issue(0); issue(1); issue(2);

    for (int it = 0; it < ITERS; it++) {
        CP_WAIT2();
        __syncthreads();
        issue(it + 3);

        const uint32_t sa = sbase + (it & 3) * STAGEB;
        #pragma unroll
        for (int kk = 0; kk < 2; kk++) {
            uint32_t ah[2][4], al[2][4], bh[4][2], bl[4][2];
            #pragma unroll
            for (int mt = 0; mt < 2; mt++) {
                uint32_t ad = sa + a_off + mt * (16 * ROWB) + kk * 32;
                ldmatrix_x4(ah[mt][0], ah[mt][1], ah[mt][2], ah[mt][3], ad);
                ldmatrix_x4(al[mt][0], al[mt][1], al[mt][2], al[mt][3], ad + TILEB);
            }
            #pragma unroll
            for (int nt = 0; nt < 4; nt++) {
                uint32_t bd = sa + 2 * TILEB + b_off + nt * (8 * ROWB) + kk * 32;
                ldmatrix_x2(bh[nt][0], bh[nt][1], bd);
                ldmatrix_x2(bl[nt][0], bl[nt][1], bd + TILEB);
            }
            #pragma unroll
            for (int mt = 0; mt < 2; mt++)
                #pragma unroll
                for (int nt = 0; nt < 4; nt++) {
                    float* cc = c[mt][nt];
                    mma_bf16(cc[0], cc[1], cc[2], cc[3],
                             ah[mt][0], ah[mt][1], ah[mt][2], ah[mt][3],
                             bh[nt][0], bh[nt][1]);
                    mma_bf16(cc[0], cc[1], cc[2], cc[3],
                             ah[mt][0], ah[mt][1], ah[mt][2], ah[mt][3],
                             bl[nt][0], bl[nt][1]);
                    mma_bf16(cc[0], cc[1], cc[2], cc[3],
                             al[mt][0], al[mt][1], al[mt][2], al[mt][3],
                             bh[nt][0], bh[nt][1]);
                }
        }
        __syncthreads();
    }

    // Epilogue
    const int er = lane >> 2;
    const int ec = (lane & 3) * 2;
    #pragma unroll
    for (int mt = 0; mt < 2; mt++) {
        const int grow = m0 + wm * 32 + mt * 16 + er;
        #pragma unroll
        for (int nt = 0; nt < 4; nt++) {
            const int gcol = n0 + wn * 32 + nt * 8 + ec;
            float2 p0 = make_float2(c[mt][nt][0], c[mt][nt][1]);
            float2 p1 = make_float2(c[mt][nt][2], c[mt][nt][3]);
            if (BIASRELU) {
                float bx = bias[gcol], by = bias[gcol + 1];
                p0.x = fmaxf(p0.x + bx, 0.f);
                p0.y = fmaxf(p0.y + by, 0.f);
                p1.x = fmaxf(p1.x + bx, 0.f);
                p1.y = fmaxf(p1.y + by, 0.f);
            }
            *reinterpret_cast<float2*>(C + (size_t)grow * D_DIM + gcol) = p0;
            *reinterpret_cast<float2*>(C + (size_t)(grow + 8) * D_DIM + gcol) = p1;
        }
    }
}

// ---------------------------------------------------------------------------
// Kernel: x[n,i,d] = sum_j relu(g[n,i,d] + g[n,j,d] + b1[d]); emit bf16 split.
// ---------------------------------------------------------------------------
__global__ __launch_bounds__(576)
void pair_kernel(const float* __restrict__ b1) {
    __shared__ float sg[B_OBJ][64];
    int n  = blockIdx.y;
    int d0 = blockIdx.x * 64;
    int tid = threadIdx.x;

    const float* gbase = g_g + (size_t)n * B_OBJ * D_DIM + d0;
    #pragma unroll
    for (int l = tid; l < B_OBJ * 64; l += 576) {
        int j = l >> 6, dl = l & 63;
        sg[j][dl] = gbase[j * D_DIM + dl];
    }
    __syncthreads();

    int ig = tid / 64;        // 0..8
    int dl = tid % 64;
    float b = b1[d0 + dl];
    float gi[4], acc[4];
    #pragma unroll
    for (int ii = 0; ii < 4; ii++) {
        gi[ii] = sg[ig * 4 + ii][dl] + b;
        acc[ii] = 0.f;
    }
    #pragma unroll
    for (int j = 0; j < B_OBJ; j++) {
        float gj = sg[j][dl];
        #pragma unroll
        for (int ii = 0; ii < 4; ii++)
            acc[ii] += fmaxf(gi[ii] + gj, 0.f);
    }
    size_t obase = (size_t)n * B_OBJ * D_DIM + d0 + dl;
    #pragma unroll
    for (int ii = 0; ii < 4; ii++) {
        __nv_bfloat16 h, l;
        split1(acc[ii], h, l);
        g_xh[obase + (size_t)(ig * 4 + ii) * D_DIM] = h;
        g_xl[obase + (size_t)(ig * 4 + ii) * D_DIM] = l;
    }
}

// ---------------------------------------------------------------------------
// Launch
// ---------------------------------------------------------------------------
extern "C" void kernel_launch(void* const* d_in, const int* in_sizes, int n_in,
                              void* d_out, int out_size) {
    const float* v  = (const float*)d_in[0];
    const float* q  = (const float*)d_in[1];
    const float* W1 = (const float*)d_in[2];
    const float* b1 = (const float*)d_in[3];
    const float* W2 = (const float*)d_in[4];
    const float* b2 = (const float*)d_in[5];
    const float* W3 = (const float*)d_in[6];
    const float* b3 = (const float*)d_in[7];
    float* out = (float*)d_out;

    float *p_g;
    __nv_bfloat16 *p_uh, *p_ul, *p_xh, *p_xl, *p_W1h, *p_W1l, *p_W2h, *p_W2l;
    cudaGetSymbolAddress((void**)&p_g,   g_g);
    cudaGetSymbolAddress((void**)&p_uh,  g_uh);
    cudaGetSymbolAddress((void**)&p_ul,  g_ul);
    cudaGetSymbolAddress((void**)&p_xh,  g_xh);
    cudaGetSymbolAddress((void**)&p_xl,  g_xl);
    cudaGetSymbolAddress((void**)&p_W1h, g_W1h);
    cudaGetSymbolAddress((void**)&p_W1l, g_W1l);
    cudaGetSymbolAddress((void**)&p_W2h, g_W2h);
    cudaGetSymbolAddress((void**)&p_W2l, g_W2l);

    cudaFuncSetAttribute(bf16_gemm<false>,
                         cudaFuncAttributeMaxDynamicSharedMemorySize, SMEM_GEMM);
    cudaFuncSetAttribute(bf16_gemm<true>,
                         cudaFuncAttributeMaxDynamicSharedMemorySize, SMEM_GEMM);

    // 1) qe = relu(q @ W3 + b3)
    qe_kernel<<<64, 256>>>(q, W3, b3);

    // 2) transpose + split weights
    wsplit<<<dim3(64, 64), dim3(32, 8)>>>(W1, p_W1h, p_W1l);
    wsplit<<<dim3(64, 64), dim3(32, 8)>>>(W2, p_W2h, p_W2l);

    // 3) u = v * qe, split to bf16 hi/lo
    usplit<<<(NB * D_DIM / 4 + 255) / 256, 256>>>(v);

    // 4) g = u @ W1^T   (fp32 out)
    bf16_gemm<false><<<dim3(16, 9), 512, SMEM_GEMM>>>(p_uh, p_ul, p_W1h, p_W1l,
                                                      nullptr, p_g);

    // 5) x = sum_j relu(g_i + g_j + b1), split to bf16 hi/lo
    pair_kernel<<<dim3(32, 32), 576>>>(b1);

    // 6) out = relu(x @ W2^T + b2)
    bf16_gemm<true><<<dim3(16, 9), 512, SMEM_GEMM>>>(p_xh, p_xl, p_W2h, p_W2l,
                                                     b2, out);
}

// round 10
// speedup vs baseline: 1.0003x; 1.0003x over previous
#include <cuda_runtime.h>
#include <cuda_bf16.h>
#include <cstdint>

// ---------------------------------------------------------------------------
// Problem dims (fixed by the dataset)
// ---------------------------------------------------------------------------
#define N_BATCH 32
#define B_OBJ   36
#define D_DIM   2048
#define Q_DIM   1024
#define NB      (N_BATCH * B_OBJ)   // 1152

// Scratch (device globals)
__device__ float          g_qe [N_BATCH * D_DIM];
__device__ float          g_g  [NB * D_DIM];        // GEMM1 out (fp32, for pair)
__device__ __nv_bfloat16  g_uh [NB * D_DIM];        // (v*qe) hi
__device__ __nv_bfloat16  g_ul [NB * D_DIM];        // (v*qe) lo
__device__ __nv_bfloat16  g_xh [NB * D_DIM];        // pair-out hi
__device__ __nv_bfloat16  g_xl [NB * D_DIM];        // pair-out lo
__device__ __nv_bfloat16  g_W1h[D_DIM * D_DIM];     // W1^T hi  [N][K]
__device__ __nv_bfloat16  g_W1l[D_DIM * D_DIM];
__device__ __nv_bfloat16  g_W2h[D_DIM * D_DIM];
__device__ __nv_bfloat16  g_W2l[D_DIM * D_DIM];

// ---------------------------------------------------------------------------
// Helpers
// ---------------------------------------------------------------------------
__device__ __forceinline__ uint32_t smem_u32(const void* p) {
    uint32_t a;
    asm("{ .reg .u64 t; cvta.to.shared.u64 t, %1; cvt.u32.u64 %0, t; }"
        : "=r"(a) : "l"(p));
    return a;
}

__device__ __forceinline__ void ldmatrix_x4(uint32_t& r0, uint32_t& r1,
                                            uint32_t& r2, uint32_t& r3,
                                            uint32_t addr) {
    asm volatile("ldmatrix.sync.aligned.m8n8.x4.shared.b16 {%0,%1,%2,%3}, [%4];"
                 : "=r"(r0), "=r"(r1), "=r"(r2), "=r"(r3) : "r"(addr));
}

__device__ __forceinline__ void ldmatrix_x2(uint32_t& r0, uint32_t& r1,
                                            uint32_t addr) {
    asm volatile("ldmatrix.sync.aligned.m8n8.x2.shared.b16 {%0,%1}, [%2];"
                 : "=r"(r0), "=r"(r1) : "r"(addr));
}

__device__ __forceinline__ void mma_bf16(float& c0, float& c1, float& c2, float& c3,
                                         uint32_t a0, uint32_t a1, uint32_t a2, uint32_t a3,
                                         uint32_t b0, uint32_t b1) {
    asm volatile(
        "mma.sync.aligned.m16n8k16.row.col.f32.bf16.bf16.f32 "
        "{%0,%1,%2,%3}, {%4,%5,%6,%7}, {%8,%9}, {%0,%1,%2,%3};"
        : "+f"(c0), "+f"(c1), "+f"(c2), "+f"(c3)
        : "r"(a0), "r"(a1), "r"(a2), "r"(a3), "r"(b0), "r"(b1));
}

__device__ __forceinline__ void cp_async16(uint32_t dst, const void* src) {
    asm volatile("cp.async.cg.shared.global [%0], [%1], 16;"
                 :: "r"(dst), "l"(src) : "memory");
}
#define CP_COMMIT() asm volatile("cp.async.commit_group;" ::: "memory")
#define CP_WAIT2()  asm volatile("cp.async.wait_group 2;"  ::: "memory")

// Split fp32 -> bf16 hi + bf16 lo
__device__ __forceinline__ void split1(float x, __nv_bfloat16& h, __nv_bfloat16& l) {
    h = __float2bfloat16(x);
    l = __float2bfloat16(x - __bfloat162float(h));
}

// ---------------------------------------------------------------------------
// Kernel 1: qe[n,d] = relu(sum_k q[n,k] * W3[k,d] + b3[d])
// ---------------------------------------------------------------------------
__global__ __launch_bounds__(256)
void qe_kernel(const float* __restrict__ q,
               const float* __restrict__ W3,
               const float* __restrict__ b3) {
    int gid = blockIdx.x * 256 + threadIdx.x;       // 0..16383
    int d  = gid & (D_DIM - 1);
    int n0 = (gid >> 11) * 4;
    float a0 = 0.f, a1 = 0.f, a2 = 0.f, a3 = 0.f;
    const float* q0 = q + (n0 + 0) * Q_DIM;
    const float* q1 = q + (n0 + 1) * Q_DIM;
    const float* q2 = q + (n0 + 2) * Q_DIM;
    const float* q3 = q + (n0 + 3) * Q_DIM;
    #pragma unroll 4
    for (int k = 0; k < Q_DIM; k++) {
        float w = W3[k * D_DIM + d];
        a0 += q0[k] * w; a1 += q1[k] * w; a2 += q2[k] * w; a3 += q3[k] * w;
    }
    float b = b3[d];
    g_qe[(n0 + 0) * D_DIM + d] = fmaxf(a0 + b, 0.f);
    g_qe[(n0 + 1) * D_DIM + d] = fmaxf(a1 + b, 0.f);
    g_qe[(n0 + 2) * D_DIM + d] = fmaxf(a2 + b, 0.f);
    g_qe[(n0 + 3) * D_DIM + d] = fmaxf(a3 + b, 0.f);
}

// ---------------------------------------------------------------------------
// Kernel 2: fused transpose + bf16 split: W [K][N] -> Wt_hi/lo [N][K]
// ---------------------------------------------------------------------------
__global__ __launch_bounds__(256)
void wsplit(const float* __restrict__ in,
            __nv_bfloat16* __restrict__ oh,
            __nv_bfloat16* __restrict__ ol) {
    __shared__ float tile[32][33];
    int x = blockIdx.x * 32 + threadIdx.x;
    int y = blockIdx.y * 32 + threadIdx.y;
    #pragma unroll
    for (int j = 0; j < 32; j += 8)
        tile[threadIdx.y + j][threadIdx.x] = in[(y + j) * D_DIM + x];
    __syncthreads();
    x = blockIdx.y * 32 + threadIdx.x;   // k index in output
    y = blockIdx.x * 32 + threadIdx.y;   // n index in output
    #pragma unroll
    for (int j = 0; j < 32; j += 8) {
        float v = tile[threadIdx.x][threadIdx.y + j];
        __nv_bfloat16 h, l;
        split1(v, h, l);
        oh[(size_t)(y + j) * D_DIM + x] = h;
        ol[(size_t)(y + j) * D_DIM + x] = l;
    }
}

// ---------------------------------------------------------------------------
// Kernel 3: u = v * qe  -> split into g_uh / g_ul
// ---------------------------------------------------------------------------
__global__ __launch_bounds__(256)
void usplit(const float* __restrict__ v) {
    int idx4 = blockIdx.x * 256 + threadIdx.x;      // float4 index
    int idx = idx4 * 4;
    if (idx >= NB * D_DIM) return;
    int row = idx / D_DIM;
    int d   = idx & (D_DIM - 1);
    int n   = row / B_OBJ;
    float4 vv = *reinterpret_cast<const float4*>(v + idx);
    float4 qq = *reinterpret_cast<const float4*>(g_qe + n * D_DIM + d);
    float u0 = vv.x * qq.x, u1 = vv.y * qq.y, u2 = vv.z * qq.z, u3 = vv.w * qq.w;
    __nv_bfloat16 h0, h1, h2, h3, l0, l1, l2, l3;
    split1(u0, h0, l0); split1(u1, h1, l1);
    split1(u2, h2, l2); split1(u3, h3, l3);
    __nv_bfloat162 ph0(h0, h1), ph1(h2, h3), pl0(l0, l1), pl1(l2, l3);
    *reinterpret_cast<__nv_bfloat162*>(g_uh + idx)     = ph0;
    *reinterpret_cast<__nv_bfloat162*>(g_uh + idx + 2) = ph1;
    *reinterpret_cast<__nv_bfloat162*>(g_ul + idx)     = pl0;
    *reinterpret_cast<__nv_bfloat162*>(g_ul + idx + 2) = pl1;
}

// ---------------------------------------------------------------------------
// GEMM: C[1152,2048] = A @ B^T using pre-split bf16 hi/lo operands.
// A rows [M][K] (hi/lo), B rows [N][K] (hi/lo).  3-term: Ah*Bh + Ah*Bl + Al*Bh.
// CTA 128x128x32, 512 threads (16 warps, 4x4), warp tile 32x32.
// cp.async 4-stage pipeline. SMEM rows padded to 80B (conflict-free ldmatrix).
// ---------------------------------------------------------------------------
constexpr int ROWB   = 80;
constexpr int TILEB  = 128 * ROWB;        // 10240
constexpr int STAGEB = 4 * TILEB;         // 40960 (Ah, Al, Bh, Bl)
constexpr int SMEM_GEMM = 4 * STAGEB;     // 163840

template<bool BIASRELU>
__global__ __launch_bounds__(512, 1)
void bf16_gemm(const __nv_bfloat16* __restrict__ Ah,
               const __nv_bfloat16* __restrict__ Al,
               const __nv_bfloat16* __restrict__ Bh,
               const __nv_bfloat16* __restrict__ Bl,
               const float* __restrict__ bias,
               float* __restrict__ C) {
    extern __shared__ char sm[];
    const uint32_t sbase = smem_u32(sm);

    const int tid  = threadIdx.x;
    const int wid  = tid >> 5;
    const int lane = tid & 31;
    const int wm   = wid >> 2;                 // 0..3
    const int wn   = wid & 3;                  // 0..3
    const int m0   = blockIdx.y * 128;
    const int n0   = blockIdx.x * 128;
    constexpr int K = 2048;
    constexpr int ITERS = K / 32;              // 64

    // cp.async assignment: row = tid>>2, chunk c = tid&3 (16B each), all 4 tiles
    const int lr = tid >> 2;
    const int lc = tid & 3;
    const char* gAh = (const char*)(Ah + (size_t)(m0 + lr) * K) + lc * 16;
    const char* gAl = (const char*)(Al + (size_t)(m0 + lr) * K) + lc * 16;
    const char* gBh = (const char*)(Bh + (size_t)(n0 + lr) * K) + lc * 16;
    const char* gBl = (const char*)(Bl + (size_t)(n0 + lr) * K) + lc * 16;
    const uint32_t sdst = sbase + lr * ROWB + lc * 16;

    auto issue = [&](int it) {
        if (it < ITERS) {
            const uint32_t st = (it & 3) * STAGEB;
            const int gk = it * 64;            // byte offset along K (32 bf16)
            cp_async16(sdst + st,             gAh + gk);
            cp_async16(sdst + st + TILEB,     gAl + gk);
            cp_async16(sdst + st + 2 * TILEB, gBh + gk);
            cp_async16(sdst + st + 3 * TILEB, gBl + gk);
        }
        CP_COMMIT();
    };

    // ldmatrix per-lane offsets
    const uint32_t a_off = (wm * 32 + (lane & 15)) * ROWB + ((lane >> 4) & 1) * 16;
    const uint32_t b_off = (wn * 32 + (lane & 7)) * ROWB + ((lane >> 3) & 1) * 16;

    float c[2][4][4];
    #pragma unroll
    for (int i = 0; i < 2; i++)
        #pragma unroll
        for (int j = 0; j < 4; j++)
            #pragma unroll
            for (int k = 0; k < 4; k++) c[i][j][k] = 0.f;

    issue(0); issue(1); issue(2);

    for (int it = 0; it < ITERS; it++) {
        CP_WAIT2();
        __syncthreads();
        issue(it + 3);

        const uint32_t sa = sbase + (it & 3) * STAGEB;
        #pragma unroll
        for (int kk = 0; kk < 2; kk++) {
            uint32_t ah[2][4], al[2][4], bh[4][2], bl[4][2];
            #pragma unroll
            for (int mt = 0; mt < 2; mt++) {
                uint32_t ad = sa + a_off + mt * (16 * ROWB) + kk * 32;
                ldmatrix_x4(ah[mt][0], ah[mt][1], ah[mt][2], ah[mt][3], ad);
                ldmatrix_x4(al[mt][0], al[mt][1], al[mt][2], al[mt][3], ad + TILEB);
            }
            #pragma unroll
            for (int nt = 0; nt < 4; nt++) {
                uint32_t bd = sa + 2 * TILEB + b_off + nt * (8 * ROWB) + kk * 32;
                ldmatrix_x2(bh[nt][0], bh[nt][1], bd);
                ldmatrix_x2(bl[nt][0], bl[nt][1], bd + TILEB);
            }
            #pragma unroll
            for (int mt = 0; mt < 2; mt++)
                #pragma unroll
                for (int nt = 0; nt < 4; nt++) {
                    float* cc = c[mt][nt];
                    mma_bf16(cc[0], cc[1], cc[2], cc[3],
                             ah[mt][0], ah[mt][1], ah[mt][2], ah[mt][3],
                             bh[nt][0], bh[nt][1]);
                    mma_bf16(cc[0], cc[1], cc[2], cc[3],
                             ah[mt][0], ah[mt][1], ah[mt][2], ah[mt][3],
                             bl[nt][0], bl[nt][1]);
                    mma_bf16(cc[0], cc[1], cc[2], cc[3],
                             al[mt][0], al[mt][1], al[mt][2], al[mt][3],
                             bh[nt][0], bh[nt][1]);
                }
        }
        __syncthreads();
    }

    // Epilogue
    const int er = lane >> 2;
    const int ec = (lane & 3) * 2;
    #pragma unroll
    for (int mt = 0; mt < 2; mt++) {
        const int grow = m0 + wm * 32 + mt * 16 + er;
        #pragma unroll
        for (int nt = 0; nt < 4; nt++) {
            const int gcol = n0 + wn * 32 + nt * 8 + ec;
            float2 p0 = make_float2(c[mt][nt][0], c[mt][nt][1]);
            float2 p1 = make_float2(c[mt][nt][2], c[mt][nt][3]);
            if (BIASRELU) {
                float bx = bias[gcol], by = bias[gcol + 1];
                p0.x = fmaxf(p0.x + bx, 0.f);
                p0.y = fmaxf(p0.y + by, 0.f);
                p1.x = fmaxf(p1.x + bx, 0.f);
                p1.y = fmaxf(p1.y + by, 0.f);
            }
            *reinterpret_cast<float2*>(C + (size_t)grow * D_DIM + gcol) = p0;
            *reinterpret_cast<float2*>(C + (size_t)(grow + 8) * D_DIM + gcol) = p1;
        }
    }
}

// ---------------------------------------------------------------------------
// Kernel: x[n,i,d] = sum_j relu(g[n,i,d] + g[n,j,d] + b1[d]); emit bf16 split.
// ---------------------------------------------------------------------------
__global__ __launch_bounds__(576)
void pair_kernel(const float* __restrict__ b1) {
    __shared__ float sg[B_OBJ][64];
    int n  = blockIdx.y;
    int d0 = blockIdx.x * 64;
    int tid = threadIdx.x;

    const float* gbase = g_g + (size_t)n * B_OBJ * D_DIM + d0;
    #pragma unroll
    for (int l = tid; l < B_OBJ * 64; l += 576) {
        int j = l >> 6, dl = l & 63;
        sg[j][dl] = gbase[j * D_DIM + dl];
    }
    __syncthreads();

    int ig = tid / 64;        // 0..8
    int dl = tid % 64;
    float b = b1[d0 + dl];
    float gi[4], acc[4];
    #pragma unroll
    for (int ii = 0; ii < 4; ii++) {
        gi[ii] = sg[ig * 4 + ii][dl] + b;
        acc[ii] = 0.f;
    }
    #pragma unroll
    for (int j = 0; j < B_OBJ; j++) {
        float gj = sg[j][dl];
        #pragma unroll
        for (int ii = 0; ii < 4; ii++)
            acc[ii] += fmaxf(gi[ii] + gj, 0.f);
    }
    size_t obase = (size_t)n * B_OBJ * D_DIM + d0 + dl;
    #pragma unroll
    for (int ii = 0; ii < 4; ii++) {
        __nv_bfloat16 h, l;
        split1(acc[ii], h, l);
        g_xh[obase + (size_t)(ig * 4 + ii) * D_DIM] = h;
        g_xl[obase + (size_t)(ig * 4 + ii) * D_DIM] = l;
    }
}

// ---------------------------------------------------------------------------
// Launch
// ---------------------------------------------------------------------------
extern "C" void kernel_launch(void* const* d_in, const int* in_sizes, int n_in,
                              void* d_out, int out_size) {
    const float* v  = (const float*)d_in[0];
    const float* q  = (const float*)d_in[1];
    const float* W1 = (const float*)d_in[2];
    const float* b1 = (const float*)d_in[3];
    const float* W2 = (const float*)d_in[4];
    const float* b2 = (const float*)d_in[5];
    const float* W3 = (const float*)d_in[6];
    const float* b3 = (const float*)d_in[7];
    float* out = (float*)d_out;

    float *p_g;
    __nv_bfloat16 *p_uh, *p_ul, *p_xh, *p_xl, *p_W1h, *p_W1l, *p_W2h, *p_W2l;
    cudaGetSymbolAddress((void**)&p_g,   g_g);
    cudaGetSymbolAddress((void**)&p_uh,  g_uh);
    cudaGetSymbolAddress((void**)&p_ul,  g_ul);
    cudaGetSymbolAddress((void**)&p_xh,  g_xh);
    cudaGetSymbolAddress((void**)&p_xl,  g_xl);
    cudaGetSymbolAddress((void**)&p_W1h, g_W1h);
    cudaGetSymbolAddress((void**)&p_W1l, g_W1l);
    cudaGetSymbolAddress((void**)&p_W2h, g_W2h);
    cudaGetSymbolAddress((void**)&p_W2l, g_W2l);

    cudaFuncSetAttribute(bf16_gemm<false>,
                         cudaFuncAttributeMaxDynamicSharedMemorySize, SMEM_GEMM);
    cudaFuncSetAttribute(bf16_gemm<true>,
                         cudaFuncAttributeMaxDynamicSharedMemorySize, SMEM_GEMM);

    // 1) qe = relu(q @ W3 + b3)
    qe_kernel<<<64, 256>>>(q, W3, b3);

    // 2) transpose + split weights
    wsplit<<<dim3(64, 64), dim3(32, 8)>>>(W1, p_W1h, p_W1l);
    wsplit<<<dim3(64, 64), dim3(32, 8)>>>(W2, p_W2h, p_W2l);

    // 3) u = v * qe, split to bf16 hi/lo
    usplit<<<(NB * D_DIM / 4 + 255) / 256, 256>>>(v);

    // 4) g = u @ W1^T   (fp32 out)
    bf16_gemm<false><<<dim3(16, 9), 512, SMEM_GEMM>>>(p_uh, p_ul, p_W1h, p_W1l,
                                                      nullptr, p_g);

    // 5) x = sum_j relu(g_i + g_j + b1), split to bf16 hi/lo
    pair_kernel<<<dim3(32, 32), 576>>>(b1);

    // 6) out = relu(x @ W2^T + b2)
    bf16_gemm<true><<<dim3(16, 9), 512, SMEM_GEMM>>>(p_xh, p_xl, p_W2h, p_W2l,
                                                     b2, out);
}

// round 11
// speedup vs baseline: 1.0129x; 1.0126x over previous
#include <cuda_runtime.h>
#include <cuda_bf16.h>
#include <cstdint>

// ---------------------------------------------------------------------------
// Problem dims (fixed by the dataset)
// ---------------------------------------------------------------------------
#define N_BATCH 32
#define B_OBJ   36
#define D_DIM   2048
#define Q_DIM   1024
#define NB      (N_BATCH * B_OBJ)   // 1152

// Scratch (device globals)
__device__ float          g_qe [N_BATCH * D_DIM];
__device__ float          g_g  [NB * D_DIM];        // GEMM1 out (fp32, for pair)
__device__ __nv_bfloat16  g_uh [NB * D_DIM];        // (v*qe) hi
__device__ __nv_bfloat16  g_ul [NB * D_DIM];        // (v*qe) lo
__device__ __nv_bfloat16  g_xh [NB * D_DIM];        // pair-out hi
__device__ __nv_bfloat16  g_xl [NB * D_DIM];        // pair-out lo
__device__ __nv_bfloat16  g_W1h[D_DIM * D_DIM];     // W1^T hi  [N][K]
__device__ __nv_bfloat16  g_W1l[D_DIM * D_DIM];
__device__ __nv_bfloat16  g_W2h[D_DIM * D_DIM];
__device__ __nv_bfloat16  g_W2l[D_DIM * D_DIM];

// ---------------------------------------------------------------------------
// Helpers
// ---------------------------------------------------------------------------
__device__ __forceinline__ uint32_t smem_u32(const void* p) {
    uint32_t a;
    asm("{ .reg .u64 t; cvta.to.shared.u64 t, %1; cvt.u32.u64 %0, t; }"
        : "=r"(a) : "l"(p));
    return a;
}

__device__ __forceinline__ void ldmatrix_x4(uint32_t& r0, uint32_t& r1,
                                            uint32_t& r2, uint32_t& r3,
                                            uint32_t addr) {
    asm volatile("ldmatrix.sync.aligned.m8n8.x4.shared.b16 {%0,%1,%2,%3}, [%4];"
                 : "=r"(r0), "=r"(r1), "=r"(r2), "=r"(r3) : "r"(addr));
}

__device__ __forceinline__ void ldmatrix_x2(uint32_t& r0, uint32_t& r1,
                                            uint32_t addr) {
    asm volatile("ldmatrix.sync.aligned.m8n8.x2.shared.b16 {%0,%1}, [%2];"
                 : "=r"(r0), "=r"(r1) : "r"(addr));
}

__device__ __forceinline__ void mma_bf16(float& c0, float& c1, float& c2, float& c3,
                                         uint32_t a0, uint32_t a1, uint32_t a2, uint32_t a3,
                                         uint32_t b0, uint32_t b1) {
    asm volatile(
        "mma.sync.aligned.m16n8k16.row.col.f32.bf16.bf16.f32 "
        "{%0,%1,%2,%3}, {%4,%5,%6,%7}, {%8,%9}, {%0,%1,%2,%3};"
        : "+f"(c0), "+f"(c1), "+f"(c2), "+f"(c3)
        : "r"(a0), "r"(a1), "r"(a2), "r"(a3), "r"(b0), "r"(b1));
}

__device__ __forceinline__ void cp_async16(uint32_t dst, const void* src) {
    asm volatile("cp.async.cg.shared.global [%0], [%1], 16;"
                 :: "r"(dst), "l"(src) : "memory");
}
#define CP_COMMIT() asm volatile("cp.async.commit_group;" ::: "memory")
#define CP_WAIT2()  asm volatile("cp.async.wait_group 2;"  ::: "memory")

// Split fp32 -> bf16 hi + bf16 lo
__device__ __forceinline__ void split1(float x, __nv_bfloat16& h, __nv_bfloat16& l) {
    h = __float2bfloat16(x);
    l = __float2bfloat16(x - __bfloat162float(h));
}

// ---------------------------------------------------------------------------
// Kernel 1: qe[n,d] = relu(sum_k q[n,k] * W3[k,d] + b3[d])
// ---------------------------------------------------------------------------
__global__ __launch_bounds__(256)
void qe_kernel(const float* __restrict__ q,
               const float* __restrict__ W3,
               const float* __restrict__ b3) {
    int gid = blockIdx.x * 256 + threadIdx.x;       // 0..16383
    int d  = gid & (D_DIM - 1);
    int n0 = (gid >> 11) * 4;
    float a0 = 0.f, a1 = 0.f, a2 = 0.f, a3 = 0.f;
    const float* q0 = q + (n0 + 0) * Q_DIM;
    const float* q1 = q + (n0 + 1) * Q_DIM;
    const float* q2 = q + (n0 + 2) * Q_DIM;
    const float* q3 = q + (n0 + 3) * Q_DIM;
    #pragma unroll 4
    for (int k = 0; k < Q_DIM; k++) {
        float w = W3[k * D_DIM + d];
        a0 += q0[k] * w; a1 += q1[k] * w; a2 += q2[k] * w; a3 += q3[k] * w;
    }
    float b = b3[d];
    g_qe[(n0 + 0) * D_DIM + d] = fmaxf(a0 + b, 0.f);
    g_qe[(n0 + 1) * D_DIM + d] = fmaxf(a1 + b, 0.f);
    g_qe[(n0 + 2) * D_DIM + d] = fmaxf(a2 + b, 0.f);
    g_qe[(n0 + 3) * D_DIM + d] = fmaxf(a3 + b, 0.f);
}

// ---------------------------------------------------------------------------
// Kernel 2: fused transpose + bf16 split: W [K][N] -> Wt_hi/lo [N][K]
// ---------------------------------------------------------------------------
__global__ __launch_bounds__(256)
void wsplit(const float* __restrict__ in,
            __nv_bfloat16* __restrict__ oh,
            __nv_bfloat16* __restrict__ ol) {
    __shared__ float tile[32][33];
    int x = blockIdx.x * 32 + threadIdx.x;
    int y = blockIdx.y * 32 + threadIdx.y;
    #pragma unroll
    for (int j = 0; j < 32; j += 8)
        tile[threadIdx.y + j][threadIdx.x] = in[(y + j) * D_DIM + x];
    __syncthreads();
    x = blockIdx.y * 32 + threadIdx.x;   // k index in output
    y = blockIdx.x * 32 + threadIdx.y;   // n index in output
    #pragma unroll
    for (int j = 0; j < 32; j += 8) {
        float v = tile[threadIdx.x][threadIdx.y + j];
        __nv_bfloat16 h, l;
        split1(v, h, l);
        oh[(size_t)(y + j) * D_DIM + x] = h;
        ol[(size_t)(y + j) * D_DIM + x] = l;
    }
}

// ---------------------------------------------------------------------------
// Kernel 3: u = v * qe  -> split into g_uh / g_ul
// ---------------------------------------------------------------------------
__global__ __launch_bounds__(256)
void usplit(const float* __restrict__ v) {
    int idx4 = blockIdx.x * 256 + threadIdx.x;      // float4 index
    int idx = idx4 * 4;
    if (idx >= NB * D_DIM) return;
    int row = idx / D_DIM;
    int d   = idx & (D_DIM - 1);
    int n   = row / B_OBJ;
    float4 vv = *reinterpret_cast<const float4*>(v + idx);
    float4 qq = *reinterpret_cast<const float4*>(g_qe + n * D_DIM + d);
    float u0 = vv.x * qq.x, u1 = vv.y * qq.y, u2 = vv.z * qq.z, u3 = vv.w * qq.w;
    __nv_bfloat16 h0, h1, h2, h3, l0, l1, l2, l3;
    split1(u0, h0, l0); split1(u1, h1, l1);
    split1(u2, h2, l2); split1(u3, h3, l3);
    __nv_bfloat162 ph0(h0, h1), ph1(h2, h3), pl0(l0, l1), pl1(l2, l3);
    *reinterpret_cast<__nv_bfloat162*>(g_uh + idx)     = ph0;
    *reinterpret_cast<__nv_bfloat162*>(g_uh + idx + 2) = ph1;
    *reinterpret_cast<__nv_bfloat162*>(g_ul + idx)     = pl0;
    *reinterpret_cast<__nv_bfloat162*>(g_ul + idx + 2) = pl1;
}

// ---------------------------------------------------------------------------
// GEMM: C[1152,2048] = A @ B^T using pre-split bf16 hi/lo operands.
// A rows [M][K] (hi/lo), B rows [N][K] (hi/lo).  3-term: Ah*Bh + Ah*Bl + Al*Bh.
// CTA 128x128x32, 512 threads (16 warps, 4x4), warp tile 32x32.
// cp.async 4-stage pipeline. SMEM rows padded to 80B (conflict-free ldmatrix).
// ---------------------------------------------------------------------------
constexpr int ROWB   = 80;
constexpr int TILEB  = 128 * ROWB;        // 10240
constexpr int STAGEB = 4 * TILEB;         // 40960 (Ah, Al, Bh, Bl)
constexpr int SMEM_GEMM = 4 * STAGEB;     // 163840

template<bool BIASRELU>
__global__ __launch_bounds__(512, 1)
void bf16_gemm(const __nv_bfloat16* __restrict__ Ah,
               const __nv_bfloat16* __restrict__ Al,
               const __nv_bfloat16* __restrict__ Bh,
               const __nv_bfloat16* __restrict__ Bl,
               const float* __restrict__ bias,
               float* __restrict__ C) {
    extern __shared__ char sm[];
    const uint32_t sbase = smem_u32(sm);

    const int tid  = threadIdx.x;
    const int wid  = tid >> 5;
    const int lane = tid & 31;
    const int wm   = wid >> 2;                 // 0..3
    const int wn   = wid & 3;                  // 0..3
    const int m0   = blockIdx.y * 128;
    const int n0   = blockIdx.x * 128;
    constexpr int K = 2048;
    constexpr int ITERS = K / 32;              // 64

    // cp.async assignment: row = tid>>2, chunk c = tid&3 (16B each), all 4 tiles
    const int lr = tid >> 2;
    const int lc = tid & 3;
    const char* gAh = (const char*)(Ah + (size_t)(m0 + lr) * K) + lc * 16;
    const char* gAl = (const char*)(Al + (size_t)(m0 + lr) * K) + lc * 16;
    const char* gBh = (const char*)(Bh + (size_t)(n0 + lr) * K) + lc * 16;
    const char* gBl = (const char*)(Bl + (size_t)(n0 + lr) * K) + lc * 16;
    const uint32_t sdst = sbase + lr * ROWB + lc * 16;

    auto issue = [&](int it) {
        if (it < ITERS) {
            const uint32_t st = (it & 3) * STAGEB;
            const int gk = it * 64;            // byte offset along K (32 bf16)
            cp_async16(sdst + st,             gAh + gk);
            cp_async16(sdst + st + TILEB,     gAl + gk);
            cp_async16(sdst + st + 2 * TILEB, gBh + gk);
            cp_async16(sdst + st + 3 * TILEB, gBl + gk);
        }
        CP_COMMIT();
    };

    // ldmatrix per-lane offsets
    const uint32_t a_off = (wm * 32 + (lane & 15)) * ROWB + ((lane >> 4) & 1) * 16;
    const uint32_t b_off = (wn * 32 + (lane & 7)) * ROWB + ((lane >> 3) & 1) * 16;

    float c[2][4][4];
    #pragma unroll
    for (int i = 0; i < 2; i++)
        #pragma unroll
        for (int j = 0; j < 4; j++)
            #pragma unroll
            for (int k = 0; k < 4; k++) c[i][j][k] = 0.f;

    issue(0); issue(1); issue(2);

    for (int it = 0; it < ITERS; it++) {
        CP_WAIT2();
        __syncthreads();
        issue(it + 3);

        const uint32_t sa = sbase + (it & 3) * STAGEB;
        #pragma unroll
        for (int kk = 0; kk < 2; kk++) {
            uint32_t ah[2][4], al[2][4], bh[4][2], bl[4][2];
            #pragma unroll
            for (int mt = 0; mt < 2; mt++) {
                uint32_t ad = sa + a_off + mt * (16 * ROWB) + kk * 32;
                ldmatrix_x4(ah[mt][0], ah[mt][1], ah[mt][2], ah[mt][3], ad);
                ldmatrix_x4(al[mt][0], al[mt][1], al[mt][2], al[mt][3], ad + TILEB);
            }
            #pragma unroll
            for (int nt = 0; nt < 4; nt++) {
                uint32_t bd = sa + 2 * TILEB + b_off + nt * (8 * ROWB) + kk * 32;
                ldmatrix_x2(bh[nt][0], bh[nt][1], bd);
                ldmatrix_x2(bl[nt][0], bl[nt][1], bd + TILEB);
            }
            #pragma unroll
            for (int mt = 0; mt < 2; mt++)
                #pragma unroll
                for (int nt = 0; nt < 4; nt++) {
                    float* cc = c[mt][nt];
                    mma_bf16(cc[0], cc[1], cc[2], cc[3],
                             ah[mt][0], ah[mt][1], ah[mt][2], ah[mt][3],
                             bh[nt][0], bh[nt][1]);
                    mma_bf16(cc[0], cc[1], cc[2], cc[3],
                             ah[mt][0], ah[mt][1], ah[mt][2], ah[mt][3],
                             bl[nt][0], bl[nt][1]);
                    mma_bf16(cc[0], cc[1], cc[2], cc[3],
                             al[mt][0], al[mt][1], al[mt][2], al[mt][3],
                             bh[nt][0], bh[nt][1]);
                }
        }
        __syncthreads();
    }

    // Epilogue
    const int er = lane >> 2;
    const int ec = (lane & 3) * 2;
    #pragma unroll
    for (int mt = 0; mt < 2; mt++) {
        const int grow = m0 + wm * 32 + mt * 16 + er;
        #pragma unroll
        for (int nt = 0; nt < 4; nt++) {
            const int gcol = n0 + wn * 32 + nt * 8 + ec;
            float2 p0 = make_float2(c[mt][nt][0], c[mt][nt][1]);
            float2 p1 = make_float2(c[mt][nt][2], c[mt][nt][3]);
            if (BIASRELU) {
                float bx = bias[gcol], by = bias[gcol + 1];
                p0.x = fmaxf(p0.x + bx, 0.f);
                p0.y = fmaxf(p0.y + by, 0.f);
                p1.x = fmaxf(p1.x + bx, 0.f);
                p1.y = fmaxf(p1.y + by, 0.f);
            }
            *reinterpret_cast<float2*>(C + (size_t)grow * D_DIM + gcol) = p0;
            *reinterpret_cast<float2*>(C + (size_t)(grow + 8) * D_DIM + gcol) = p1;
        }
    }
}

// ---------------------------------------------------------------------------
// Kernel: x[n,i,d] = sum_j relu(g[n,i,d] + g[n,j,d] + b1[d]); emit bf16 split.
// ---------------------------------------------------------------------------
__global__ __launch_bounds__(576)
void pair_kernel(const float* __restrict__ b1) {
    __shared__ float sg[B_OBJ][64];
    int n  = blockIdx.y;
    int d0 = blockIdx.x * 64;
    int tid = threadIdx.x;

    const float* gbase = g_g + (size_t)n * B_OBJ * D_DIM + d0;
    #pragma unroll
    for (int l = tid; l < B_OBJ * 64; l += 576) {
        int j = l >> 6, dl = l & 63;
        sg[j][dl] = gbase[j * D_DIM + dl];
    }
    __syncthreads();

    int ig = tid / 64;        // 0..8
    int dl = tid % 64;
    float b = b1[d0 + dl];
    float gi[4], acc[4];
    #pragma unroll
    for (int ii = 0; ii < 4; ii++) {
        gi[ii] = sg[ig * 4 + ii][dl] + b;
        acc[ii] = 0.f;
    }
    #pragma unroll
    for (int j = 0; j < B_OBJ; j++) {
        float gj = sg[j][dl];
        #pragma unroll
        for (int ii = 0; ii < 4; ii++)
            acc[ii] += fmaxf(gi[ii] + gj, 0.f);
    }
    size_t obase = (size_t)n * B_OBJ * D_DIM + d0 + dl;
    #pragma unroll
    for (int ii = 0; ii < 4; ii++) {
        __nv_bfloat16 h, l;
        split1(acc[ii], h, l);
        g_xh[obase + (size_t)(ig * 4 + ii) * D_DIM] = h;
        g_xl[obase + (size_t)(ig * 4 + ii) * D_DIM] = l;
    }
}

// ---------------------------------------------------------------------------
// Launch
// ---------------------------------------------------------------------------
extern "C" void kernel_launch(void* const* d_in, const int* in_sizes, int n_in,
                              void* d_out, int out_size) {
    const float* v  = (const float*)d_in[0];
    const float* q  = (const float*)d_in[1];
    const float* W1 = (const float*)d_in[2];
    const float* b1 = (const float*)d_in[3];
    const float* W2 = (const float*)d_in[4];
    const float* b2 = (const float*)d_in[5];
    const float* W3 = (const float*)d_in[6];
    const float* b3 = (const float*)d_in[7];
    float* out = (float*)d_out;

    float *p_g;
    __nv_bfloat16 *p_uh, *p_ul, *p_xh, *p_xl, *p_W1h, *p_W1l, *p_W2h, *p_W2l;
    cudaGetSymbolAddress((void**)&p_g,   g_g);
    cudaGetSymbolAddress((void**)&p_uh,  g_uh);
    cudaGetSymbolAddress((void**)&p_ul,  g_ul);
    cudaGetSymbolAddress((void**)&p_xh,  g_xh);
    cudaGetSymbolAddress((void**)&p_xl,  g_xl);
    cudaGetSymbolAddress((void**)&p_W1h, g_W1h);
    cudaGetSymbolAddress((void**)&p_W1l, g_W1l);
    cudaGetSymbolAddress((void**)&p_W2h, g_W2h);
    cudaGetSymbolAddress((void**)&p_W2l, g_W2l);

    cudaFuncSetAttribute(bf16_gemm<false>,
                         cudaFuncAttributeMaxDynamicSharedMemorySize, SMEM_GEMM);
    cudaFuncSetAttribute(bf16_gemm<true>,
                         cudaFuncAttributeMaxDynamicSharedMemorySize, SMEM_GEMM);

    // 1) qe = relu(q @ W3 + b3)
    qe_kernel<<<64, 256>>>(q, W3, b3);

    // 2) transpose + split weights
    wsplit<<<dim3(64, 64), dim3(32, 8)>>>(W1, p_W1h, p_W1l);
    wsplit<<<dim3(64, 64), dim3(32, 8)>>>(W2, p_W2h, p_W2l);

    // 3) u = v * qe, split to bf16 hi/lo
    usplit<<<(NB * D_DIM / 4 + 255) / 256, 256>>>(v);

    // 4) g = u @ W1^T   (fp32 out)
    bf16_gemm<false><<<dim3(16, 9), 512, SMEM_GEMM>>>(p_uh, p_ul, p_W1h, p_W1l,
                                                      nullptr, p_g);

    // 5) x = sum_j relu(g_i + g_j + b1), split to bf16 hi/lo
    pair_kernel<<<dim3(32, 32), 576>>>(b1);

    // 6) out = relu(x @ W2^T + b2)
    bf16_gemm<true><<<dim3(16, 9), 512, SMEM_GEMM>>>(p_xh, p_xl, p_W2h, p_W2l,
                                                     b2, out);
}

// round 12
// speedup vs baseline: 1.0145x; 1.0016x over previous
#include <cuda_runtime.h>
#include <cuda_bf16.h>
#include <cstdint>

// ---------------------------------------------------------------------------
// Problem dims (fixed by the dataset)
// ---------------------------------------------------------------------------
#define N_BATCH 32
#define B_OBJ   36
#define D_DIM   2048
#define Q_DIM   1024
#define NB      (N_BATCH * B_OBJ)   // 1152

// Scratch (device globals)
__device__ float          g_qe [N_BATCH * D_DIM];
__device__ float          g_g  [NB * D_DIM];        // GEMM1 out (fp32, for pair)
__device__ __nv_bfloat16  g_uh [NB * D_DIM];        // (v*qe) hi
__device__ __nv_bfloat16  g_ul [NB * D_DIM];        // (v*qe) lo
__device__ __nv_bfloat16  g_xh [NB * D_DIM];        // pair-out hi
__device__ __nv_bfloat16  g_xl [NB * D_DIM];        // pair-out lo
__device__ __nv_bfloat16  g_W1h[D_DIM * D_DIM];     // W1^T hi  [N][K]
__device__ __nv_bfloat16  g_W1l[D_DIM * D_DIM];
__device__ __nv_bfloat16  g_W2h[D_DIM * D_DIM];
__device__ __nv_bfloat16  g_W2l[D_DIM * D_DIM];

// ---------------------------------------------------------------------------
// Helpers
// ---------------------------------------------------------------------------
__device__ __forceinline__ uint32_t smem_u32(const void* p) {
    uint32_t a;
    asm("{ .reg .u64 t; cvta.to.shared.u64 t, %1; cvt.u32.u64 %0, t; }"
        : "=r"(a) : "l"(p));
    return a;
}

__device__ __forceinline__ void ldmatrix_x4(uint32_t& r0, uint32_t& r1,
                                            uint32_t& r2, uint32_t& r3,
                                            uint32_t addr) {
    asm volatile("ldmatrix.sync.aligned.m8n8.x4.shared.b16 {%0,%1,%2,%3}, [%4];"
                 : "=r"(r0), "=r"(r1), "=r"(r2), "=r"(r3) : "r"(addr));
}

__device__ __forceinline__ void ldmatrix_x2(uint32_t& r0, uint32_t& r1,
                                            uint32_t addr) {
    asm volatile("ldmatrix.sync.aligned.m8n8.x2.shared.b16 {%0,%1}, [%2];"
                 : "=r"(r0), "=r"(r1) : "r"(addr));
}

__device__ __forceinline__ void mma_bf16(float& c0, float& c1, float& c2, float& c3,
                                         uint32_t a0, uint32_t a1, uint32_t a2, uint32_t a3,
                                         uint32_t b0, uint32_t b1) {
    asm volatile(
        "mma.sync.aligned.m16n8k16.row.col.f32.bf16.bf16.f32 "
        "{%0,%1,%2,%3}, {%4,%5,%6,%7}, {%8,%9}, {%0,%1,%2,%3};"
        : "+f"(c0), "+f"(c1), "+f"(c2), "+f"(c3)
        : "r"(a0), "r"(a1), "r"(a2), "r"(a3), "r"(b0), "r"(b1));
}

__device__ __forceinline__ void cp_async16(uint32_t dst, const void* src) {
    asm volatile("cp.async.cg.shared.global [%0], [%1], 16;"
                 :: "r"(dst), "l"(src) : "memory");
}
#define CP_COMMIT() asm volatile("cp.async.commit_group;" ::: "memory")
#define CP_WAIT2()  asm volatile("cp.async.wait_group 2;"  ::: "memory")

// Split fp32 -> bf16 hi + bf16 lo
__device__ __forceinline__ void split1(float x, __nv_bfloat16& h, __nv_bfloat16& l) {
    h = __float2bfloat16(x);
    l = __float2bfloat16(x - __bfloat162float(h));
}

// ---------------------------------------------------------------------------
// Kernel 1: qe[n,d] = relu(sum_k q[n,k] * W3[k,d] + b3[d])
// ---------------------------------------------------------------------------
__global__ __launch_bounds__(256)
void qe_kernel(const float* __restrict__ q,
               const float* __restrict__ W3,
               const float* __restrict__ b3) {
    int gid = blockIdx.x * 256 + threadIdx.x;       // 0..16383
    int d  = gid & (D_DIM - 1);
    int n0 = (gid >> 11) * 4;
    float a0 = 0.f, a1 = 0.f, a2 = 0.f, a3 = 0.f;
    const float* q0 = q + (n0 + 0) * Q_DIM;
    const float* q1 = q + (n0 + 1) * Q_DIM;
    const float* q2 = q + (n0 + 2) * Q_DIM;
    const float* q3 = q + (n0 + 3) * Q_DIM;
    #pragma unroll 4
    for (int k = 0; k < Q_DIM; k++) {
        float w = W3[k * D_DIM + d];
        a0 += q0[k] * w; a1 += q1[k] * w; a2 += q2[k] * w; a3 += q3[k] * w;
    }
    float b = b3[d];
    g_qe[(n0 + 0) * D_DIM + d] = fmaxf(a0 + b, 0.f);
    g_qe[(n0 + 1) * D_DIM + d] = fmaxf(a1 + b, 0.f);
    g_qe[(n0 + 2) * D_DIM + d] = fmaxf(a2 + b, 0.f);
    g_qe[(n0 + 3) * D_DIM + d] = fmaxf(a3 + b, 0.f);
}

// ---------------------------------------------------------------------------
// Kernel 2: fused transpose + bf16 split: W [K][N] -> Wt_hi/lo [N][K]
// ---------------------------------------------------------------------------
__global__ __launch_bounds__(256)
void wsplit(const float* __restrict__ in,
            __nv_bfloat16* __restrict__ oh,
            __nv_bfloat16* __restrict__ ol) {
    __shared__ float tile[32][33];
    int x = blockIdx.x * 32 + threadIdx.x;
    int y = blockIdx.y * 32 + threadIdx.y;
    #pragma unroll
    for (int j = 0; j < 32; j += 8)
        tile[threadIdx.y + j][threadIdx.x] = in[(y + j) * D_DIM + x];
    __syncthreads();
    x = blockIdx.y * 32 + threadIdx.x;   // k index in output
    y = blockIdx.x * 32 + threadIdx.y;   // n index in output
    #pragma unroll
    for (int j = 0; j < 32; j += 8) {
        float v = tile[threadIdx.x][threadIdx.y + j];
        __nv_bfloat16 h, l;
        split1(v, h, l);
        oh[(size_t)(y + j) * D_DIM + x] = h;
        ol[(size_t)(y + j) * D_DIM + x] = l;
    }
}

// ---------------------------------------------------------------------------
// Kernel 3: u = v * qe  -> split into g_uh / g_ul
// ---------------------------------------------------------------------------
__global__ __launch_bounds__(256)
void usplit(const float* __restrict__ v) {
    int idx4 = blockIdx.x * 256 + threadIdx.x;      // float4 index
    int idx = idx4 * 4;
    if (idx >= NB * D_DIM) return;
    int row = idx / D_DIM;
    int d   = idx & (D_DIM - 1);
    int n   = row / B_OBJ;
    float4 vv = *reinterpret_cast<const float4*>(v + idx);
    float4 qq = *reinterpret_cast<const float4*>(g_qe + n * D_DIM + d);
    float u0 = vv.x * qq.x, u1 = vv.y * qq.y, u2 = vv.z * qq.z, u3 = vv.w * qq.w;
    __nv_bfloat16 h0, h1, h2, h3, l0, l1, l2, l3;
    split1(u0, h0, l0); split1(u1, h1, l1);
    split1(u2, h2, l2); split1(u3, h3, l3);
    __nv_bfloat162 ph0(h0, h1), ph1(h2, h3), pl0(l0, l1), pl1(l2, l3);
    *reinterpret_cast<__nv_bfloat162*>(g_uh + idx)     = ph0;
    *reinterpret_cast<__nv_bfloat162*>(g_uh + idx + 2) = ph1;
    *reinterpret_cast<__nv_bfloat162*>(g_ul + idx)     = pl0;
    *reinterpret_cast<__nv_bfloat162*>(g_ul + idx + 2) = pl1;
}

// ---------------------------------------------------------------------------
// GEMM: C[1152,2048] = A @ B^T using pre-split bf16 hi/lo operands.
// A rows [M][K] (hi/lo), B rows [N][K] (hi/lo).  3-term: Ah*Bh + Ah*Bl + Al*Bh.
// CTA 128x128x32, 512 threads (16 warps, 4x4), warp tile 32x32.
// cp.async 4-stage pipeline. SMEM rows padded to 80B (conflict-free ldmatrix).
// ---------------------------------------------------------------------------
constexpr int ROWB   = 80;
constexpr int TILEB  = 128 * ROWB;        // 10240
constexpr int STAGEB = 4 * TILEB;         // 40960 (Ah, Al, Bh, Bl)
constexpr int SMEM_GEMM = 4 * STAGEB;     // 163840

template<bool BIASRELU>
__global__ __launch_bounds__(512, 1)
void bf16_gemm(const __nv_bfloat16* __restrict__ Ah,
               const __nv_bfloat16* __restrict__ Al,
               const __nv_bfloat16* __restrict__ Bh,
               const __nv_bfloat16* __restrict__ Bl,
               const float* __restrict__ bias,
               float* __restrict__ C) {
    extern __shared__ char sm[];
    const uint32_t sbase = smem_u32(sm);

    const int tid  = threadIdx.x;
    const int wid  = tid >> 5;
    const int lane = tid & 31;
    const int wm   = wid >> 2;                 // 0..3
    const int wn   = wid & 3;                  // 0..3
    const int m0   = blockIdx.y * 128;
    const int n0   = blockIdx.x * 128;
    constexpr int K = 2048;
    constexpr int ITERS = K / 32;              // 64

    // cp.async assignment: row = tid>>2, chunk c = tid&3 (16B each), all 4 tiles
    const int lr = tid >> 2;
    const int lc = tid & 3;
    const char* gAh = (const char*)(Ah + (size_t)(m0 + lr) * K) + lc * 16;
    const char* gAl = (const char*)(Al + (size_t)(m0 + lr) * K) + lc * 16;
    const char* gBh = (const char*)(Bh + (size_t)(n0 + lr) * K) + lc * 16;
    const char* gBl = (const char*)(Bl + (size_t)(n0 + lr) * K) + lc * 16;
    const uint32_t sdst = sbase + lr * ROWB + lc * 16;

    auto issue = [&](int it) {
        if (it < ITERS) {
            const uint32_t st = (it & 3) * STAGEB;
            const int gk = it * 64;            // byte offset along K (32 bf16)
            cp_async16(sdst + st,             gAh + gk);
            cp_async16(sdst + st + TILEB,     gAl + gk);
            cp_async16(sdst + st + 2 * TILEB, gBh + gk);
            cp_async16(sdst + st + 3 * TILEB, gBl + gk);
        }
        CP_COMMIT();
    };

    // ldmatrix per-lane offsets
    const uint32_t a_off = (wm * 32 + (lane & 15)) * ROWB + ((lane >> 4) & 1) * 16;
    const uint32_t b_off = (wn * 32 + (lane & 7)) * ROWB + ((lane >> 3) & 1) * 16;

    float c[2][4][4];
    #pragma unroll
    for (int i = 0; i < 2; i++)
        #pragma unroll
        for (int j = 0; j < 4; j++)
            #pragma unroll
            for (int k = 0; k < 4; k++) c[i][j][k] = 0.f;

    issue(0); issue(1); issue(2);

    for (int it = 0; it < ITERS; it++) {
        CP_WAIT2();
        __syncthreads();
        issue(it + 3);

        const uint32_t sa = sbase + (it & 3) * STAGEB;
        #pragma unroll
        for (int kk = 0; kk < 2; kk++) {
            uint32_t ah[2][4], al[2][4], bh[4][2], bl[4][2];
            #pragma unroll
            for (int mt = 0; mt < 2; mt++) {
                uint32_t ad = sa + a_off + mt * (16 * ROWB) + kk * 32;
                ldmatrix_x4(ah[mt][0], ah[mt][1], ah[mt][2], ah[mt][3], ad);
                ldmatrix_x4(al[mt][0], al[mt][1], al[mt][2], al[mt][3], ad + TILEB);
            }
            #pragma unroll
            for (int nt = 0; nt < 4; nt++) {
                uint32_t bd = sa + 2 * TILEB + b_off + nt * (8 * ROWB) + kk * 32;
                ldmatrix_x2(bh[nt][0], bh[nt][1], bd);
                ldmatrix_x2(bl[nt][0], bl[nt][1], bd + TILEB);
            }
            #pragma unroll
            for (int mt = 0; mt < 2; mt++)
                #pragma unroll
                for (int nt = 0; nt < 4; nt++) {
                    float* cc = c[mt][nt];
                    mma_bf16(cc[0], cc[1], cc[2], cc[3],
                             ah[mt][0], ah[mt][1], ah[mt][2], ah[mt][3],
                             bh[nt][0], bh[nt][1]);
                    mma_bf16(cc[0], cc[1], cc[2], cc[3],
                             ah[mt][0], ah[mt][1], ah[mt][2], ah[mt][3],
                             bl[nt][0], bl[nt][1]);
                    mma_bf16(cc[0], cc[1], cc[2], cc[3],
                             al[mt][0], al[mt][1], al[mt][2], al[mt][3],
                             bh[nt][0], bh[nt][1]);
                }
        }
        __syncthreads();
    }

    // Epilogue
    const int er = lane >> 2;
    const int ec = (lane & 3) * 2;
    #pragma unroll
    for (int mt = 0; mt < 2; mt++) {
        const int grow = m0 + wm * 32 + mt * 16 + er;
        #pragma unroll
        for (int nt = 0; nt < 4; nt++) {
            const int gcol = n0 + wn * 32 + nt * 8 + ec;
            float2 p0 = make_float2(c[mt][nt][0], c[mt][nt][1]);
            float2 p1 = make_float2(c[mt][nt][2], c[mt][nt][3]);
            if (BIASRELU) {
                float bx = bias[gcol], by = bias[gcol + 1];
                p0.x = fmaxf(p0.x + bx, 0.f);
                p0.y = fmaxf(p0.y + by, 0.f);
                p1.x = fmaxf(p1.x + bx, 0.f);
                p1.y = fmaxf(p1.y + by, 0.f);
            }
            *reinterpret_cast<float2*>(C + (size_t)grow * D_DIM + gcol) = p0;
            *reinterpret_cast<float2*>(C + (size_t)(grow + 8) * D_DIM + gcol) = p1;
        }
    }
}

// ---------------------------------------------------------------------------
// Kernel: x[n,i,d] = sum_j relu(g[n,i,d] + g[n,j,d] + b1[d]); emit bf16 split.
// ---------------------------------------------------------------------------
__global__ __launch_bounds__(576)
void pair_kernel(const float* __restrict__ b1) {
    __shared__ float sg[B_OBJ][64];
    int n  = blockIdx.y;
    int d0 = blockIdx.x * 64;
    int tid = threadIdx.x;

    const float* gbase = g_g + (size_t)n * B_OBJ * D_DIM + d0;
    #pragma unroll
    for (int l = tid; l < B_OBJ * 64; l += 576) {
        int j = l >> 6, dl = l & 63;
        sg[j][dl] = gbase[j * D_DIM + dl];
    }
    __syncthreads();

    int ig = tid / 64;        // 0..8
    int dl = tid % 64;
    float b = b1[d0 + dl];
    float gi[4], acc[4];
    #pragma unroll
    for (int ii = 0; ii < 4; ii++) {
        gi[ii] = sg[ig * 4 + ii][dl] + b;
        acc[ii] = 0.f;
    }
    #pragma unroll
    for (int j = 0; j < B_OBJ; j++) {
        float gj = sg[j][dl];
        #pragma unroll
        for (int ii = 0; ii < 4; ii++)
            acc[ii] += fmaxf(gi[ii] + gj, 0.f);
    }
    size_t obase = (size_t)n * B_OBJ * D_DIM + d0 + dl;
    #pragma unroll
    for (int ii = 0; ii < 4; ii++) {
        __nv_bfloat16 h, l;
        split1(acc[ii], h, l);
        g_xh[obase + (size_t)(ig * 4 + ii) * D_DIM] = h;
        g_xl[obase + (size_t)(ig * 4 + ii) * D_DIM] = l;
    }
}

// ---------------------------------------------------------------------------
// Launch
// ---------------------------------------------------------------------------
extern "C" void kernel_launch(void* const* d_in, const int* in_sizes, int n_in,
                              void* d_out, int out_size) {
    const float* v  = (const float*)d_in[0];
    const float* q  = (const float*)d_in[1];
    const float* W1 = (const float*)d_in[2];
    const float* b1 = (const float*)d_in[3];
    const float* W2 = (const float*)d_in[4];
    const float* b2 = (const float*)d_in[5];
    const float* W3 = (const float*)d_in[6];
    const float* b3 = (const float*)d_in[7];
    float* out = (float*)d_out;

    float *p_g;
    __nv_bfloat16 *p_uh, *p_ul, *p_xh, *p_xl, *p_W1h, *p_W1l, *p_W2h, *p_W2l;
    cudaGetSymbolAddress((void**)&p_g,   g_g);
    cudaGetSymbolAddress((void**)&p_uh,  g_uh);
    cudaGetSymbolAddress((void**)&p_ul,  g_ul);
    cudaGetSymbolAddress((void**)&p_xh,  g_xh);
    cudaGetSymbolAddress((void**)&p_xl,  g_xl);
    cudaGetSymbolAddress((void**)&p_W1h, g_W1h);
    cudaGetSymbolAddress((void**)&p_W1l, g_W1l);
    cudaGetSymbolAddress((void**)&p_W2h, g_W2h);
    cudaGetSymbolAddress((void**)&p_W2l, g_W2l);

    cudaFuncSetAttribute(bf16_gemm<false>,
                         cudaFuncAttributeMaxDynamicSharedMemorySize, SMEM_GEMM);
    cudaFuncSetAttribute(bf16_gemm<true>,
                         cudaFuncAttributeMaxDynamicSharedMemorySize, SMEM_GEMM);

    // 1) qe = relu(q @ W3 + b3)
    qe_kernel<<<64, 256>>>(q, W3, b3);

    // 2) transpose + split weights
    wsplit<<<dim3(64, 64), dim3(32, 8)>>>(W1, p_W1h, p_W1l);
    wsplit<<<dim3(64, 64), dim3(32, 8)>>>(W2, p_W2h, p_W2l);

    // 3) u = v * qe, split to bf16 hi/lo
    usplit<<<(NB * D_DIM / 4 + 255) / 256, 256>>>(v);

    // 4) g = u @ W1^T   (fp32 out)
    bf16_gemm<false><<<dim3(16, 9), 512, SMEM_GEMM>>>(p_uh, p_ul, p_W1h, p_W1l,
                                                      nullptr, p_g);

    // 5) x = sum_j relu(g_i + g_j + b1), split to bf16 hi/lo
    pair_kernel<<<dim3(32, 32), 576>>>(b1);

    // 6) out = relu(x @ W2^T + b2)
    bf16_gemm<true><<<dim3(16, 9), 512, SMEM_GEMM>>>(p_xh, p_xl, p_W2h, p_W2l,
                                                     b2, out);
}